// round 10
// baseline (speedup 1.0000x reference)
#include <cuda_runtime.h>
#include <cuda_bf16.h>
#include <math.h>
#include <stdint.h>

#define N_NODES 50000
#define N_EDGES 800000
#define DIM 128
#define HEADS 4
#define OUTF 32
#define NEG_SLOPE 0.2f

#define SCAN_B 1024
#define SCAN_NB ((N_NODES + SCAN_B - 1) / SCAN_B)   // 49

// ---------------- scratch ----------------
__device__ int   g_counts[N_NODES];
__device__ int   g_rowptr[N_NODES + 1];
__device__ int   g_cursor[N_NODES];
__device__ int   g_colsrc[N_EDGES];
__device__ float g_w_am[N_EDGES];
__device__ float g_w_ph[N_EDGES];
__device__ float g_ft_am[N_NODES * DIM];
__device__ float g_ft_ph[N_NODES * DIM];
__device__ float g_h_am[N_NODES * DIM];
__device__ float g_h_ph[N_NODES * DIM];
__device__ float g_el_am[N_NODES * HEADS];
__device__ float g_er_am[N_NODES * HEADS];
__device__ float g_el_ph[N_NODES * HEADS];
__device__ float g_er_ph[N_NODES * HEADS];
__device__ int   g_bsum[SCAN_NB];
__device__ int   g_bsumex[SCAN_NB];

__device__ __forceinline__ uint32_t tf32_rna(float x) {
    uint32_t r;
    asm("cvt.rna.tf32.f32 %0, %1;" : "=r"(r) : "f"(x));
    return r;
}

// ---------------- CSR build ----------------
__global__ void zero_counts_kernel() {
    int i = blockIdx.x * blockDim.x + threadIdx.x;
    if (i < N_NODES) g_counts[i] = 0;
}

__global__ void hist_kernel(const int* __restrict__ dst) {
    int e = blockIdx.x * blockDim.x + threadIdx.x;
    if (e < N_EDGES) atomicAdd(&g_counts[dst[e]], 1);
}

__global__ void scan_partial_kernel() {
    __shared__ int smem[256];
    int b = blockIdx.x, t = threadIdx.x;
    int base = b * SCAN_B;
    int s = 0;
    #pragma unroll
    for (int j = 0; j < 4; j++) {
        int i = base + t + j * 256;
        if (i < N_NODES) s += g_counts[i];
    }
    smem[t] = s;
    __syncthreads();
    for (int off = 128; off > 0; off >>= 1) {
        if (t < off) smem[t] += smem[t + off];
        __syncthreads();
    }
    if (t == 0) g_bsum[b] = smem[0];
}

__global__ void scan_bsum_kernel() {
    __shared__ int smem[64];
    int t = threadIdx.x;
    int v = (t < SCAN_NB) ? g_bsum[t] : 0;
    smem[t] = v;
    __syncthreads();
    #pragma unroll
    for (int off = 1; off < 64; off <<= 1) {
        int x = (t >= off) ? smem[t - off] : 0;
        __syncthreads();
        smem[t] += x;
        __syncthreads();
    }
    if (t < SCAN_NB) g_bsumex[t] = smem[t] - v;
}

__global__ void scan_write_kernel() {
    __shared__ int smem[SCAN_B];
    int b = blockIdx.x, t = threadIdx.x;
    int i = b * SCAN_B + t;
    int v = (i < N_NODES) ? g_counts[i] : 0;
    smem[t] = v;
    __syncthreads();
    #pragma unroll
    for (int off = 1; off < SCAN_B; off <<= 1) {
        int x = (t >= off) ? smem[t - off] : 0;
        __syncthreads();
        smem[t] += x;
        __syncthreads();
    }
    int excl = smem[t] - v + g_bsumex[b];
    if (i < N_NODES) {
        g_rowptr[i] = excl;
        g_cursor[i] = excl;
        if (i == N_NODES - 1) g_rowptr[N_NODES] = excl + v;
    }
}

__global__ void scatter_kernel(const int* __restrict__ src, const int* __restrict__ dst,
                               const float* __restrict__ am_w, const float* __restrict__ ph_w) {
    int e = blockIdx.x * blockDim.x + threadIdx.x;
    if (e >= N_EDGES) return;
    int d = dst[e];
    int pos = atomicAdd(&g_cursor[d], 1);
    g_colsrc[pos] = src[e];
    g_w_am[pos] = am_w[e];
    g_w_ph[pos] = ph_w[e];
}

// ---------------- tf32 mma.sync GEMM + fused el/er epilogue ----------------
#define A_STRIDE 132
#define W_STRIDE 136
#define GEMM_SMEM_FLOATS (128 * A_STRIDE + 128 * W_STRIDE + 256)
#define GEMM_SMEM_BYTES (GEMM_SMEM_FLOATS * 4)

__global__ void __launch_bounds__(256, 1) gemm_tf32_kernel(
    const float* __restrict__ A, const float* __restrict__ W,
    const float* __restrict__ al, const float* __restrict__ ar,
    float* __restrict__ C, float* __restrict__ el, float* __restrict__ er, int M)
{
    extern __shared__ float sm[];
    float* Asm = sm;
    float* Wsm = sm + 128 * A_STRIDE;
    float* als = Wsm + 128 * W_STRIDE;
    float* ars = als + 128;

    int tid = threadIdx.x;
    int br = blockIdx.x * 128;

    #pragma unroll
    for (int i = 0; i < 16; i++) {
        int idx = tid + i * 256;
        int row = idx >> 5;
        int c4 = (idx & 31) * 4;
        int gr = br + row;
        float4 v = make_float4(0.f, 0.f, 0.f, 0.f);
        if (gr < M) v = *reinterpret_cast<const float4*>(&A[(size_t)gr * 128 + c4]);
        float* p = &Asm[row * A_STRIDE + c4];
        p[0] = __uint_as_float(tf32_rna(v.x));
        p[1] = __uint_as_float(tf32_rna(v.y));
        p[2] = __uint_as_float(tf32_rna(v.z));
        p[3] = __uint_as_float(tf32_rna(v.w));
    }
    #pragma unroll
    for (int i = 0; i < 16; i++) {
        int idx = tid + i * 256;
        int row = idx >> 5;
        int c4 = (idx & 31) * 4;
        float4 v = *reinterpret_cast<const float4*>(&W[(size_t)row * 128 + c4]);
        float* p = &Wsm[row * W_STRIDE + c4];
        p[0] = __uint_as_float(tf32_rna(v.x));
        p[1] = __uint_as_float(tf32_rna(v.y));
        p[2] = __uint_as_float(tf32_rna(v.z));
        p[3] = __uint_as_float(tf32_rna(v.w));
    }
    if (tid < 32) {
        *reinterpret_cast<float4*>(&als[tid * 4]) = *reinterpret_cast<const float4*>(&al[tid * 4]);
        *reinterpret_cast<float4*>(&ars[tid * 4]) = *reinterpret_cast<const float4*>(&ar[tid * 4]);
    }
    __syncthreads();

    int w = tid >> 5;
    int lane = tid & 31;
    int g = lane >> 2;
    int q = lane & 3;
    int lrow0 = w * 16 + g;
    int lrow1 = lrow0 + 8;

    float acc[16][4];
    #pragma unroll
    for (int j = 0; j < 16; j++) {
        acc[j][0] = 0.f; acc[j][1] = 0.f; acc[j][2] = 0.f; acc[j][3] = 0.f;
    }

    #pragma unroll
    for (int kk = 0; kk < 16; kk++) {
        int k0 = kk * 8;
        uint32_t a0 = __float_as_uint(Asm[lrow0 * A_STRIDE + k0 + q]);
        uint32_t a1 = __float_as_uint(Asm[lrow1 * A_STRIDE + k0 + q]);
        uint32_t a2 = __float_as_uint(Asm[lrow0 * A_STRIDE + k0 + q + 4]);
        uint32_t a3 = __float_as_uint(Asm[lrow1 * A_STRIDE + k0 + q + 4]);
        #pragma unroll
        for (int j = 0; j < 16; j++) {
            uint32_t b0 = __float_as_uint(Wsm[(k0 + q) * W_STRIDE + 8 * j + g]);
            uint32_t b1 = __float_as_uint(Wsm[(k0 + q + 4) * W_STRIDE + 8 * j + g]);
            asm volatile(
                "mma.sync.aligned.m16n8k8.row.col.f32.tf32.tf32.f32 "
                "{%0,%1,%2,%3}, {%4,%5,%6,%7}, {%8,%9}, {%0,%1,%2,%3};"
                : "+f"(acc[j][0]), "+f"(acc[j][1]), "+f"(acc[j][2]), "+f"(acc[j][3])
                : "r"(a0), "r"(a1), "r"(a2), "r"(a3), "r"(b0), "r"(b1));
        }
    }

    int grow0 = br + lrow0;
    int grow1 = br + lrow1;

    float el0[4] = {0.f, 0.f, 0.f, 0.f}, er0[4] = {0.f, 0.f, 0.f, 0.f};
    float el1[4] = {0.f, 0.f, 0.f, 0.f}, er1[4] = {0.f, 0.f, 0.f, 0.f};

    #pragma unroll
    for (int j = 0; j < 16; j++) {
        int c = 8 * j + 2 * q;
        int h = j >> 2;
        float w0 = als[c], w1 = als[c + 1];
        float r0 = ars[c], r1 = ars[c + 1];
        el0[h] += acc[j][0] * w0 + acc[j][1] * w1;
        er0[h] += acc[j][0] * r0 + acc[j][1] * r1;
        el1[h] += acc[j][2] * w0 + acc[j][3] * w1;
        er1[h] += acc[j][2] * r0 + acc[j][3] * r1;
        if (grow0 < M)
            *reinterpret_cast<float2*>(&C[(size_t)grow0 * 128 + c]) = make_float2(acc[j][0], acc[j][1]);
        if (grow1 < M)
            *reinterpret_cast<float2*>(&C[(size_t)grow1 * 128 + c]) = make_float2(acc[j][2], acc[j][3]);
    }

    #pragma unroll
    for (int h = 0; h < 4; h++) {
        #pragma unroll
        for (int off = 1; off < 4; off <<= 1) {
            el0[h] += __shfl_xor_sync(0xffffffffu, el0[h], off);
            er0[h] += __shfl_xor_sync(0xffffffffu, er0[h], off);
            el1[h] += __shfl_xor_sync(0xffffffffu, el1[h], off);
            er1[h] += __shfl_xor_sync(0xffffffffu, er1[h], off);
        }
    }
    if (q == 0) {
        if (grow0 < M) {
            *reinterpret_cast<float4*>(&el[grow0 * 4]) = make_float4(el0[0], el0[1], el0[2], el0[3]);
            *reinterpret_cast<float4*>(&er[grow0 * 4]) = make_float4(er0[0], er0[1], er0[2], er0[3]);
        }
        if (grow1 < M) {
            *reinterpret_cast<float4*>(&el[grow1 * 4]) = make_float4(el1[0], el1[1], el1[2], el1[3]);
            *reinterpret_cast<float4*>(&er[grow1 * 4]) = make_float4(er1[0], er1[1], er1[2], er1[3]);
        }
    }
}

// ---------------- leaky ----------------
__device__ __forceinline__ float leaky(float v) {
    return v > 0.f ? v : NEG_SLOPE * v;
}

// ---------------- dual-branch fused softmax + aggregation: warp per node ----------------
// Phase A: lane-parallel alpha for BOTH branches, staged to smem.
// Phase B: serial edge loop, broadcast LDS, 8 gathers per edge (double MLP).
#define AGG_WARPS 8
template <bool LAYER1>
__global__ void __launch_bounds__(AGG_WARPS * 32) fused_agg2_kernel(
    const float* __restrict__ ftA, const float* __restrict__ ftP,
    const float* __restrict__ elA, const float* __restrict__ erA,
    const float* __restrict__ elP, const float* __restrict__ erP,
    const float* __restrict__ biasA, const float* __restrict__ biasP,
    float* __restrict__ outA, float* __restrict__ outP)
{
    __shared__ int   s_src[AGG_WARPS][32];
    __shared__ float4 s_xa[AGG_WARPS][32];
    __shared__ float4 s_xp[AGG_WARPS][32];

    int i = (blockIdx.x * blockDim.x + threadIdx.x) >> 5;
    int wslot = threadIdx.x >> 5;
    int lane = threadIdx.x & 31;
    if (i >= N_NODES) return;
    int beg = g_rowptr[i], end = g_rowptr[i + 1];

    float4 ea = *reinterpret_cast<const float4*>(erA + i * 4);
    float4 ep = *reinterpret_cast<const float4*>(erP + i * 4);

    float aA0 = 0.f, aA1 = 0.f, aA2 = 0.f, aA3 = 0.f;   // am feature accum
    float aP0 = 0.f, aP1 = 0.f, aP2 = 0.f, aP3 = 0.f;   // ph feature accum
    float dA0 = 0.f, dA1 = 0.f, dA2 = 0.f, dA3 = 0.f;   // am denom
    float dP0 = 0.f, dP1 = 0.f, dP2 = 0.f, dP3 = 0.f;   // ph denom

    for (int chunk = beg; chunk < end; chunk += 32) {
        int n = end - chunk;
        if (n > 32) n = 32;

        // ---- phase A: lane-parallel alpha for both branches ----
        int s = 0;
        float4 xwa = make_float4(0.f, 0.f, 0.f, 0.f);
        float4 xwp = make_float4(0.f, 0.f, 0.f, 0.f);
        if (lane < n) {
            int e = chunk + lane;
            s = g_colsrc[e];
            float wa = g_w_am[e];
            float wp = g_w_ph[e];
            float4 la = *reinterpret_cast<const float4*>(elA + s * 4);
            float4 lp = *reinterpret_cast<const float4*>(elP + s * 4);
            float x0 = __expf(leaky(la.x + ea.x));
            float x1 = __expf(leaky(la.y + ea.y));
            float x2 = __expf(leaky(la.z + ea.z));
            float x3 = __expf(leaky(la.w + ea.w));
            float y0 = __expf(leaky(lp.x + ep.x));
            float y1 = __expf(leaky(lp.y + ep.y));
            float y2 = __expf(leaky(lp.z + ep.z));
            float y3 = __expf(leaky(lp.w + ep.w));
            dA0 += x0; dA1 += x1; dA2 += x2; dA3 += x3;
            dP0 += y0; dP1 += y1; dP2 += y2; dP3 += y3;
            xwa = make_float4(x0 * wa, x1 * wa, x2 * wa, x3 * wa);
            xwp = make_float4(y0 * wp, y1 * wp, y2 * wp, y3 * wp);
        }
        s_src[wslot][lane] = s;
        s_xa[wslot][lane] = xwa;
        s_xp[wslot][lane] = xwp;
        __syncwarp();

        // ---- phase B: broadcast + dual gather, 2-way unrolled ----
        int j = 0;
        for (; j + 1 < n; j += 2) {
            int s0 = s_src[wslot][j];
            int s1 = s_src[wslot][j + 1];
            float4 a0 = s_xa[wslot][j];
            float4 a1 = s_xa[wslot][j + 1];
            float4 p0 = s_xp[wslot][j];
            float4 p1 = s_xp[wslot][j + 1];
            const float* fa0 = ftA + (size_t)s0 * DIM;
            const float* fa1 = ftA + (size_t)s1 * DIM;
            const float* fp0 = ftP + (size_t)s0 * DIM;
            const float* fp1 = ftP + (size_t)s1 * DIM;
            float va00 = fa0[lane], va01 = fa0[32 + lane], va02 = fa0[64 + lane], va03 = fa0[96 + lane];
            float va10 = fa1[lane], va11 = fa1[32 + lane], va12 = fa1[64 + lane], va13 = fa1[96 + lane];
            float vp00 = fp0[lane], vp01 = fp0[32 + lane], vp02 = fp0[64 + lane], vp03 = fp0[96 + lane];
            float vp10 = fp1[lane], vp11 = fp1[32 + lane], vp12 = fp1[64 + lane], vp13 = fp1[96 + lane];
            aA0 += a0.x * va00 + a1.x * va10;
            aA1 += a0.y * va01 + a1.y * va11;
            aA2 += a0.z * va02 + a1.z * va12;
            aA3 += a0.w * va03 + a1.w * va13;
            aP0 += p0.x * vp00 + p1.x * vp10;
            aP1 += p0.y * vp01 + p1.y * vp11;
            aP2 += p0.z * vp02 + p1.z * vp12;
            aP3 += p0.w * vp03 + p1.w * vp13;
        }
        if (j < n) {
            int s0 = s_src[wslot][j];
            float4 a0 = s_xa[wslot][j];
            float4 p0 = s_xp[wslot][j];
            const float* fa0 = ftA + (size_t)s0 * DIM;
            const float* fp0 = ftP + (size_t)s0 * DIM;
            aA0 += a0.x * fa0[lane];
            aA1 += a0.y * fa0[32 + lane];
            aA2 += a0.z * fa0[64 + lane];
            aA3 += a0.w * fa0[96 + lane];
            aP0 += p0.x * fp0[lane];
            aP1 += p0.y * fp0[32 + lane];
            aP2 += p0.z * fp0[64 + lane];
            aP3 += p0.w * fp0[96 + lane];
        }
        __syncwarp();
    }

    // reduce denominators across lanes
    #pragma unroll
    for (int off = 16; off > 0; off >>= 1) {
        dA0 += __shfl_xor_sync(0xffffffffu, dA0, off);
        dA1 += __shfl_xor_sync(0xffffffffu, dA1, off);
        dA2 += __shfl_xor_sync(0xffffffffu, dA2, off);
        dA3 += __shfl_xor_sync(0xffffffffu, dA3, off);
        dP0 += __shfl_xor_sync(0xffffffffu, dP0, off);
        dP1 += __shfl_xor_sync(0xffffffffu, dP1, off);
        dP2 += __shfl_xor_sync(0xffffffffu, dP2, off);
        dP3 += __shfl_xor_sync(0xffffffffu, dP3, off);
    }
    dA0 = fmaxf(dA0, 1e-9f); dA1 = fmaxf(dA1, 1e-9f);
    dA2 = fmaxf(dA2, 1e-9f); dA3 = fmaxf(dA3, 1e-9f);
    dP0 = fmaxf(dP0, 1e-9f); dP1 = fmaxf(dP1, 1e-9f);
    dP2 = fmaxf(dP2, 1e-9f); dP3 = fmaxf(dP3, 1e-9f);

    float vA0 = aA0 / dA0 + biasA[lane];
    float vA1 = aA1 / dA1 + biasA[32 + lane];
    float vA2 = aA2 / dA2 + biasA[64 + lane];
    float vA3 = aA3 / dA3 + biasA[96 + lane];
    float vP0 = aP0 / dP0 + biasP[lane];
    float vP1 = aP1 / dP1 + biasP[32 + lane];
    float vP2 = aP2 / dP2 + biasP[64 + lane];
    float vP3 = aP3 / dP3 + biasP[96 + lane];

    if (!LAYER1) {
        outA[(size_t)i * 128 + lane]      = fmaxf(vA0, 0.f);
        outA[(size_t)i * 128 + 32 + lane] = fmaxf(vA1, 0.f);
        outA[(size_t)i * 128 + 64 + lane] = fmaxf(vA2, 0.f);
        outA[(size_t)i * 128 + 96 + lane] = fmaxf(vA3, 0.f);
        outP[(size_t)i * 128 + lane]      = fmaxf(vP0, 0.f);
        outP[(size_t)i * 128 + 32 + lane] = fmaxf(vP1, 0.f);
        outP[(size_t)i * 128 + 64 + lane] = fmaxf(vP2, 0.f);
        outP[(size_t)i * 128 + 96 + lane] = fmaxf(vP3, 0.f);
    } else {
        outA[(size_t)i * 32 + lane] = 0.25f * (vA0 + vA1 + vA2 + vA3);
        outP[(size_t)i * 32 + lane] = 0.25f * (vP0 + vP1 + vP2 + vP3);
    }
}

// ---------------- launch ----------------
extern "C" void kernel_launch(void* const* d_in, const int* in_sizes, int n_in,
                              void* d_out, int out_size) {
    const float *x_am, *x_ph, *exist, *am_exist;
    const int *src, *dst;
    const float *W0a, *al0a, *ar0a, *b0a, *W0p, *al0p, *ar0p, *b0p;
    const float *W1a, *al1a, *ar1a, *b1a, *W1p, *al1p, *ar1p, *b1p;

    x_am = (const float*)d_in[0];
    x_ph = (const float*)d_in[1];
    exist = (const float*)d_in[2];
    am_exist = (const float*)d_in[3];

    if (in_sizes[4] == N_EDGES) {
        src = (const int*)d_in[4];
        dst = (const int*)d_in[5];
        W0a = (const float*)d_in[6];  al0a = (const float*)d_in[7];
        ar0a = (const float*)d_in[8]; b0a = (const float*)d_in[9];
        W0p = (const float*)d_in[10]; al0p = (const float*)d_in[11];
        ar0p = (const float*)d_in[12]; b0p = (const float*)d_in[13];
        W1a = (const float*)d_in[14]; al1a = (const float*)d_in[15];
        ar1a = (const float*)d_in[16]; b1a = (const float*)d_in[17];
        W1p = (const float*)d_in[18]; al1p = (const float*)d_in[19];
        ar1p = (const float*)d_in[20]; b1p = (const float*)d_in[21];
    } else {
        W0a = (const float*)d_in[4];  al0a = (const float*)d_in[5];
        ar0a = (const float*)d_in[6]; b0a = (const float*)d_in[7];
        W0p = (const float*)d_in[8];  al0p = (const float*)d_in[9];
        ar0p = (const float*)d_in[10]; b0p = (const float*)d_in[11];
        W1a = (const float*)d_in[12]; al1a = (const float*)d_in[13];
        ar1a = (const float*)d_in[14]; b1a = (const float*)d_in[15];
        W1p = (const float*)d_in[16]; al1p = (const float*)d_in[17];
        ar1p = (const float*)d_in[18]; b1p = (const float*)d_in[19];
        src = (const int*)d_in[20];
        dst = (const int*)d_in[21];
    }

    float* out = (float*)d_out;

    float *p_ftA, *p_ftP, *p_hA, *p_hP;
    float *p_elA, *p_erA, *p_elP, *p_erP;
    cudaGetSymbolAddress((void**)&p_ftA, g_ft_am);
    cudaGetSymbolAddress((void**)&p_ftP, g_ft_ph);
    cudaGetSymbolAddress((void**)&p_hA, g_h_am);
    cudaGetSymbolAddress((void**)&p_hP, g_h_ph);
    cudaGetSymbolAddress((void**)&p_elA, g_el_am);
    cudaGetSymbolAddress((void**)&p_erA, g_er_am);
    cudaGetSymbolAddress((void**)&p_elP, g_el_ph);
    cudaGetSymbolAddress((void**)&p_erP, g_er_ph);

    cudaFuncSetAttribute(gemm_tf32_kernel, cudaFuncAttributeMaxDynamicSharedMemorySize, GEMM_SMEM_BYTES);

    const int TB = 256;
    int gb_nodes = (N_NODES + TB - 1) / TB;
    int gb_edges = (N_EDGES + TB - 1) / TB;
    int gb_warp_nodes = (N_NODES * 32 + TB - 1) / TB;
    int gemm_blocks = (N_NODES + 127) / 128;

    // CSR build (shared by all 4 convs)
    zero_counts_kernel<<<gb_nodes, TB>>>();
    hist_kernel<<<gb_edges, TB>>>(dst);
    scan_partial_kernel<<<SCAN_NB, 256>>>();
    scan_bsum_kernel<<<1, 64>>>();
    scan_write_kernel<<<SCAN_NB, SCAN_B>>>();
    scatter_kernel<<<gb_edges, TB>>>(src, dst, am_exist, exist);

    // ---- layer 0: both branches ----
    gemm_tf32_kernel<<<gemm_blocks, 256, GEMM_SMEM_BYTES>>>(x_am, W0a, al0a, ar0a, p_ftA, p_elA, p_erA, N_NODES);
    gemm_tf32_kernel<<<gemm_blocks, 256, GEMM_SMEM_BYTES>>>(x_ph, W0p, al0p, ar0p, p_ftP, p_elP, p_erP, N_NODES);
    fused_agg2_kernel<false><<<gb_warp_nodes, TB>>>(p_ftA, p_ftP, p_elA, p_erA, p_elP, p_erP,
                                                    b0a, b0p, p_hA, p_hP);

    // ---- layer 1: both branches ----
    gemm_tf32_kernel<<<gemm_blocks, 256, GEMM_SMEM_BYTES>>>(p_hA, W1a, al1a, ar1a, p_ftA, p_elA, p_erA, N_NODES);
    gemm_tf32_kernel<<<gemm_blocks, 256, GEMM_SMEM_BYTES>>>(p_hP, W1p, al1p, ar1p, p_ftP, p_elP, p_erP, N_NODES);
    fused_agg2_kernel<true><<<gb_warp_nodes, TB>>>(p_ftA, p_ftP, p_elA, p_erA, p_elP, p_erP,
                                                   b1a, b1p, out, out + (size_t)N_NODES * OUTF);
}

// round 13
// speedup vs baseline: 1.1633x; 1.1633x over previous
#include <cuda_runtime.h>
#include <cuda_bf16.h>
#include <cuda_fp16.h>
#include <math.h>
#include <stdint.h>

#define N_NODES 50000
#define N_EDGES 800000
#define DIM 128
#define HEADS 4
#define OUTF 32
#define NEG_SLOPE 0.2f

#define SCAN_B 1024
#define SCAN_NB ((N_NODES + SCAN_B - 1) / SCAN_B)   // 49

// ---------------- scratch ----------------
__device__ int    g_counts[N_NODES];
__device__ int    g_rowptr[N_NODES + 1];
__device__ int    g_cursor[N_NODES];
__device__ int    g_colsrc[N_EDGES];
__device__ float  g_w_am[N_EDGES];
__device__ float  g_w_ph[N_EDGES];
__device__ __half g_ftH[N_NODES * DIM];     // fp16 features (gather payload)
__device__ float  g_h[N_NODES * DIM];       // fp32 hidden (GEMM input)
__device__ float  g_el[N_NODES * HEADS];
__device__ float  g_er[N_NODES * HEADS];
__device__ int    g_bsum[SCAN_NB];
__device__ int    g_bsumex[SCAN_NB];

__device__ __forceinline__ uint32_t tf32_rna(float x) {
    uint32_t r;
    asm("cvt.rna.tf32.f32 %0, %1;" : "=r"(r) : "f"(x));
    return r;
}

// ---------------- CSR build ----------------
__global__ void zero_counts_kernel() {
    int i = blockIdx.x * blockDim.x + threadIdx.x;
    if (i < N_NODES) g_counts[i] = 0;
}

__global__ void hist_kernel(const int* __restrict__ dst) {
    int e = blockIdx.x * blockDim.x + threadIdx.x;
    if (e < N_EDGES) atomicAdd(&g_counts[dst[e]], 1);
}

__global__ void scan_partial_kernel() {
    __shared__ int smem[256];
    int b = blockIdx.x, t = threadIdx.x;
    int base = b * SCAN_B;
    int s = 0;
    #pragma unroll
    for (int j = 0; j < 4; j++) {
        int i = base + t + j * 256;
        if (i < N_NODES) s += g_counts[i];
    }
    smem[t] = s;
    __syncthreads();
    for (int off = 128; off > 0; off >>= 1) {
        if (t < off) smem[t] += smem[t + off];
        __syncthreads();
    }
    if (t == 0) g_bsum[b] = smem[0];
}

__global__ void scan_bsum_kernel() {
    __shared__ int smem[64];
    int t = threadIdx.x;
    int v = (t < SCAN_NB) ? g_bsum[t] : 0;
    smem[t] = v;
    __syncthreads();
    #pragma unroll
    for (int off = 1; off < 64; off <<= 1) {
        int x = (t >= off) ? smem[t - off] : 0;
        __syncthreads();
        smem[t] += x;
        __syncthreads();
    }
    if (t < SCAN_NB) g_bsumex[t] = smem[t] - v;
}

__global__ void scan_write_kernel() {
    __shared__ int smem[SCAN_B];
    int b = blockIdx.x, t = threadIdx.x;
    int i = b * SCAN_B + t;
    int v = (i < N_NODES) ? g_counts[i] : 0;
    smem[t] = v;
    __syncthreads();
    #pragma unroll
    for (int off = 1; off < SCAN_B; off <<= 1) {
        int x = (t >= off) ? smem[t - off] : 0;
        __syncthreads();
        smem[t] += x;
        __syncthreads();
    }
    int excl = smem[t] - v + g_bsumex[b];
    if (i < N_NODES) {
        g_rowptr[i] = excl;
        g_cursor[i] = excl;
        if (i == N_NODES - 1) g_rowptr[N_NODES] = excl + v;
    }
}

__global__ void scatter_kernel(const int* __restrict__ src, const int* __restrict__ dst,
                               const float* __restrict__ am_w, const float* __restrict__ ph_w) {
    int e = blockIdx.x * blockDim.x + threadIdx.x;
    if (e >= N_EDGES) return;
    int d = dst[e];
    int pos = atomicAdd(&g_cursor[d], 1);
    g_colsrc[pos] = src[e];
    g_w_am[pos] = am_w[e];
    g_w_ph[pos] = ph_w[e];
}

// ---------------- tf32 mma.sync GEMM + fused el/er epilogue, fp16 ft output ----------------
#define A_STRIDE 132
#define W_STRIDE 136
#define GEMM_SMEM_FLOATS (128 * A_STRIDE + 128 * W_STRIDE + 256)
#define GEMM_SMEM_BYTES (GEMM_SMEM_FLOATS * 4)

__global__ void __launch_bounds__(256, 1) gemm_tf32_kernel(
    const float* __restrict__ A, const float* __restrict__ W,
    const float* __restrict__ al, const float* __restrict__ ar,
    __half* __restrict__ C, float* __restrict__ el, float* __restrict__ er, int M)
{
    extern __shared__ float sm[];
    float* Asm = sm;
    float* Wsm = sm + 128 * A_STRIDE;
    float* als = Wsm + 128 * W_STRIDE;
    float* ars = als + 128;

    int tid = threadIdx.x;
    int br = blockIdx.x * 128;

    #pragma unroll
    for (int i = 0; i < 16; i++) {
        int idx = tid + i * 256;
        int row = idx >> 5;
        int c4 = (idx & 31) * 4;
        int gr = br + row;
        float4 v = make_float4(0.f, 0.f, 0.f, 0.f);
        if (gr < M) v = *reinterpret_cast<const float4*>(&A[(size_t)gr * 128 + c4]);
        float* p = &Asm[row * A_STRIDE + c4];
        p[0] = __uint_as_float(tf32_rna(v.x));
        p[1] = __uint_as_float(tf32_rna(v.y));
        p[2] = __uint_as_float(tf32_rna(v.z));
        p[3] = __uint_as_float(tf32_rna(v.w));
    }
    #pragma unroll
    for (int i = 0; i < 16; i++) {
        int idx = tid + i * 256;
        int row = idx >> 5;
        int c4 = (idx & 31) * 4;
        float4 v = *reinterpret_cast<const float4*>(&W[(size_t)row * 128 + c4]);
        float* p = &Wsm[row * W_STRIDE + c4];
        p[0] = __uint_as_float(tf32_rna(v.x));
        p[1] = __uint_as_float(tf32_rna(v.y));
        p[2] = __uint_as_float(tf32_rna(v.z));
        p[3] = __uint_as_float(tf32_rna(v.w));
    }
    if (tid < 32) {
        *reinterpret_cast<float4*>(&als[tid * 4]) = *reinterpret_cast<const float4*>(&al[tid * 4]);
        *reinterpret_cast<float4*>(&ars[tid * 4]) = *reinterpret_cast<const float4*>(&ar[tid * 4]);
    }
    __syncthreads();

    int w = tid >> 5;
    int lane = tid & 31;
    int g = lane >> 2;
    int q = lane & 3;
    int lrow0 = w * 16 + g;
    int lrow1 = lrow0 + 8;

    float acc[16][4];
    #pragma unroll
    for (int j = 0; j < 16; j++) {
        acc[j][0] = 0.f; acc[j][1] = 0.f; acc[j][2] = 0.f; acc[j][3] = 0.f;
    }

    #pragma unroll
    for (int kk = 0; kk < 16; kk++) {
        int k0 = kk * 8;
        uint32_t a0 = __float_as_uint(Asm[lrow0 * A_STRIDE + k0 + q]);
        uint32_t a1 = __float_as_uint(Asm[lrow1 * A_STRIDE + k0 + q]);
        uint32_t a2 = __float_as_uint(Asm[lrow0 * A_STRIDE + k0 + q + 4]);
        uint32_t a3 = __float_as_uint(Asm[lrow1 * A_STRIDE + k0 + q + 4]);
        #pragma unroll
        for (int j = 0; j < 16; j++) {
            uint32_t b0 = __float_as_uint(Wsm[(k0 + q) * W_STRIDE + 8 * j + g]);
            uint32_t b1 = __float_as_uint(Wsm[(k0 + q + 4) * W_STRIDE + 8 * j + g]);
            asm volatile(
                "mma.sync.aligned.m16n8k8.row.col.f32.tf32.tf32.f32 "
                "{%0,%1,%2,%3}, {%4,%5,%6,%7}, {%8,%9}, {%0,%1,%2,%3};"
                : "+f"(acc[j][0]), "+f"(acc[j][1]), "+f"(acc[j][2]), "+f"(acc[j][3])
                : "r"(a0), "r"(a1), "r"(a2), "r"(a3), "r"(b0), "r"(b1));
        }
    }

    int grow0 = br + lrow0;
    int grow1 = br + lrow1;

    float el0[4] = {0.f, 0.f, 0.f, 0.f}, er0[4] = {0.f, 0.f, 0.f, 0.f};
    float el1[4] = {0.f, 0.f, 0.f, 0.f}, er1[4] = {0.f, 0.f, 0.f, 0.f};

    __half2* Ch = reinterpret_cast<__half2*>(C);

    #pragma unroll
    for (int j = 0; j < 16; j++) {
        int c = 8 * j + 2 * q;
        int h = j >> 2;
        float w0 = als[c], w1 = als[c + 1];
        float r0 = ars[c], r1 = ars[c + 1];
        el0[h] += acc[j][0] * w0 + acc[j][1] * w1;
        er0[h] += acc[j][0] * r0 + acc[j][1] * r1;
        el1[h] += acc[j][2] * w0 + acc[j][3] * w1;
        er1[h] += acc[j][2] * r0 + acc[j][3] * r1;
        int h2idx = c >> 1;   // 4j + q
        if (grow0 < M)
            Ch[(size_t)grow0 * 64 + h2idx] = __floats2half2_rn(acc[j][0], acc[j][1]);
        if (grow1 < M)
            Ch[(size_t)grow1 * 64 + h2idx] = __floats2half2_rn(acc[j][2], acc[j][3]);
    }

    #pragma unroll
    for (int h = 0; h < 4; h++) {
        #pragma unroll
        for (int off = 1; off < 4; off <<= 1) {
            el0[h] += __shfl_xor_sync(0xffffffffu, el0[h], off);
            er0[h] += __shfl_xor_sync(0xffffffffu, er0[h], off);
            el1[h] += __shfl_xor_sync(0xffffffffu, el1[h], off);
            er1[h] += __shfl_xor_sync(0xffffffffu, er1[h], off);
        }
    }
    if (q == 0) {
        if (grow0 < M) {
            *reinterpret_cast<float4*>(&el[grow0 * 4]) = make_float4(el0[0], el0[1], el0[2], el0[3]);
            *reinterpret_cast<float4*>(&er[grow0 * 4]) = make_float4(er0[0], er0[1], er0[2], er0[3]);
        }
        if (grow1 < M) {
            *reinterpret_cast<float4*>(&el[grow1 * 4]) = make_float4(el1[0], el1[1], el1[2], el1[3]);
            *reinterpret_cast<float4*>(&er[grow1 * 4]) = make_float4(er1[0], er1[1], er1[2], er1[3]);
        }
    }
}

// ---------------- leaky ----------------
__device__ __forceinline__ float leaky(float v) {
    return v > 0.f ? v : NEG_SLOPE * v;
}

// ---------------- fused softmax + aggregation: warp per node, fp16 gathers ----------------
// half2 index `lane`    = global features 2*lane, 2*lane+1   (head = lane/16, 0 or 1)
// half2 index `32+lane` = global features 64+2*lane, 64+2*lane+1 (head = 2 + lane/16)
template <bool LAYER1>
__global__ void fused_agg_kernel(const __half2* __restrict__ ftH,
                                 const float* __restrict__ el, const float* __restrict__ er,
                                 const float* __restrict__ w,
                                 const float* __restrict__ bias,
                                 float* __restrict__ out) {
    int i = (blockIdx.x * blockDim.x + threadIdx.x) >> 5;
    int lane = threadIdx.x & 31;
    if (i >= N_NODES) return;
    int beg = g_rowptr[i], end = g_rowptr[i + 1];
    float4 e4 = *reinterpret_cast<const float4*>(er + i * 4);
    bool hiHalf = (lane >= 16);

    float accLo_x = 0.f, accLo_y = 0.f;   // features 2lane, 2lane+1 (head 0/1)
    float accHi_x = 0.f, accHi_y = 0.f;   // features 64+2lane, 64+2lane+1 (head 2/3)
    float d0 = 0.f, d1 = 0.f, d2 = 0.f, d3 = 0.f;

    for (int chunk = beg; chunk < end; chunk += 32) {
        int n = end - chunk;
        if (n > 32) n = 32;

        // phase A: lane-parallel alpha
        int s = 0;
        float xwLo = 0.f, xwHi = 0.f, xw1 = 0.f, xw3 = 0.f;
        // store all four alphas for broadcast; pack as float4 (x0w,x1w,x2w,x3w)
        float a0 = 0.f, a1 = 0.f, a2 = 0.f, a3 = 0.f;
        if (lane < n) {
            int e = chunk + lane;
            s = g_colsrc[e];
            float we = w[e];
            float4 lv = *reinterpret_cast<const float4*>(el + s * 4);
            float x0 = __expf(leaky(lv.x + e4.x));
            float x1 = __expf(leaky(lv.y + e4.y));
            float x2 = __expf(leaky(lv.z + e4.z));
            float x3 = __expf(leaky(lv.w + e4.w));
            d0 += x0; d1 += x1; d2 += x2; d3 += x3;
            a0 = x0 * we; a1 = x1 * we; a2 = x2 * we; a3 = x3 * we;
        }
        (void)xwLo; (void)xwHi; (void)xw1; (void)xw3;

        // phase B: broadcast + gather, 2-way unrolled (2 LDG.32 per edge)
        int j = 0;
        for (; j + 1 < n; j += 2) {
            int sA = __shfl_sync(0xffffffffu, s, j);
            int sB = __shfl_sync(0xffffffffu, s, j + 1);
            float aA0 = __shfl_sync(0xffffffffu, a0, j);
            float aA1 = __shfl_sync(0xffffffffu, a1, j);
            float aA2 = __shfl_sync(0xffffffffu, a2, j);
            float aA3 = __shfl_sync(0xffffffffu, a3, j);
            float aB0 = __shfl_sync(0xffffffffu, a0, j + 1);
            float aB1 = __shfl_sync(0xffffffffu, a1, j + 1);
            float aB2 = __shfl_sync(0xffffffffu, a2, j + 1);
            float aB3 = __shfl_sync(0xffffffffu, a3, j + 1);
            float aALo = hiHalf ? aA1 : aA0;
            float aAHi = hiHalf ? aA3 : aA2;
            float aBLo = hiHalf ? aB1 : aB0;
            float aBHi = hiHalf ? aB3 : aB2;
            const __half2* fA = ftH + (size_t)sA * 64;
            const __half2* fB = ftH + (size_t)sB * 64;
            float2 vALo = __half22float2(fA[lane]);
            float2 vAHi = __half22float2(fA[32 + lane]);
            float2 vBLo = __half22float2(fB[lane]);
            float2 vBHi = __half22float2(fB[32 + lane]);
            accLo_x += aALo * vALo.x + aBLo * vBLo.x;
            accLo_y += aALo * vALo.y + aBLo * vBLo.y;
            accHi_x += aAHi * vAHi.x + aBHi * vBHi.x;
            accHi_y += aAHi * vAHi.y + aBHi * vBHi.y;
        }
        if (j < n) {
            int sA = __shfl_sync(0xffffffffu, s, j);
            float aA0 = __shfl_sync(0xffffffffu, a0, j);
            float aA1 = __shfl_sync(0xffffffffu, a1, j);
            float aA2 = __shfl_sync(0xffffffffu, a2, j);
            float aA3 = __shfl_sync(0xffffffffu, a3, j);
            float aALo = hiHalf ? aA1 : aA0;
            float aAHi = hiHalf ? aA3 : aA2;
            const __half2* fA = ftH + (size_t)sA * 64;
            float2 vALo = __half22float2(fA[lane]);
            float2 vAHi = __half22float2(fA[32 + lane]);
            accLo_x += aALo * vALo.x;
            accLo_y += aALo * vALo.y;
            accHi_x += aAHi * vAHi.x;
            accHi_y += aAHi * vAHi.y;
        }
    }

    // reduce denominators across lanes
    #pragma unroll
    for (int off = 16; off > 0; off >>= 1) {
        d0 += __shfl_xor_sync(0xffffffffu, d0, off);
        d1 += __shfl_xor_sync(0xffffffffu, d1, off);
        d2 += __shfl_xor_sync(0xffffffffu, d2, off);
        d3 += __shfl_xor_sync(0xffffffffu, d3, off);
    }
    d0 = fmaxf(d0, 1e-9f); d1 = fmaxf(d1, 1e-9f);
    d2 = fmaxf(d2, 1e-9f); d3 = fmaxf(d3, 1e-9f);

    float dLo = hiHalf ? d1 : d0;
    float dHi = hiHalf ? d3 : d2;

    int fLo = 2 * lane;        // global feature index of accLo_x
    int fHi = 64 + 2 * lane;   // global feature index of accHi_x

    float vLo_x = accLo_x / dLo + bias[fLo];
    float vLo_y = accLo_y / dLo + bias[fLo + 1];
    float vHi_x = accHi_x / dHi + bias[fHi];
    float vHi_y = accHi_y / dHi + bias[fHi + 1];

    if (!LAYER1) {
        *reinterpret_cast<float2*>(&out[(size_t)i * 128 + fLo]) =
            make_float2(fmaxf(vLo_x, 0.f), fmaxf(vLo_y, 0.f));
        *reinterpret_cast<float2*>(&out[(size_t)i * 128 + fHi]) =
            make_float2(fmaxf(vHi_x, 0.f), fmaxf(vHi_y, 0.f));
    } else {
        // mean over heads: lane l<16 holds head0+head2 for feat 2l; lane l+16 holds head1+head3
        float ux = vLo_x + vHi_x;
        float uy = vLo_y + vHi_y;
        ux += __shfl_xor_sync(0xffffffffu, ux, 16);
        uy += __shfl_xor_sync(0xffffffffu, uy, 16);
        if (lane < 16) {
            *reinterpret_cast<float2*>(&out[(size_t)i * 32 + 2 * lane]) =
                make_float2(0.25f * ux, 0.25f * uy);
        }
    }
}

// ---------------- launch ----------------
extern "C" void kernel_launch(void* const* d_in, const int* in_sizes, int n_in,
                              void* d_out, int out_size) {
    const float *x_am, *x_ph, *exist, *am_exist;
    const int *src, *dst;
    const float *W0a, *al0a, *ar0a, *b0a, *W0p, *al0p, *ar0p, *b0p;
    const float *W1a, *al1a, *ar1a, *b1a, *W1p, *al1p, *ar1p, *b1p;

    x_am = (const float*)d_in[0];
    x_ph = (const float*)d_in[1];
    exist = (const float*)d_in[2];
    am_exist = (const float*)d_in[3];

    if (in_sizes[4] == N_EDGES) {
        src = (const int*)d_in[4];
        dst = (const int*)d_in[5];
        W0a = (const float*)d_in[6];  al0a = (const float*)d_in[7];
        ar0a = (const float*)d_in[8]; b0a = (const float*)d_in[9];
        W0p = (const float*)d_in[10]; al0p = (const float*)d_in[11];
        ar0p = (const float*)d_in[12]; b0p = (const float*)d_in[13];
        W1a = (const float*)d_in[14]; al1a = (const float*)d_in[15];
        ar1a = (const float*)d_in[16]; b1a = (const float*)d_in[17];
        W1p = (const float*)d_in[18]; al1p = (const float*)d_in[19];
        ar1p = (const float*)d_in[20]; b1p = (const float*)d_in[21];
    } else {
        W0a = (const float*)d_in[4];  al0a = (const float*)d_in[5];
        ar0a = (const float*)d_in[6]; b0a = (const float*)d_in[7];
        W0p = (const float*)d_in[8];  al0p = (const float*)d_in[9];
        ar0p = (const float*)d_in[10]; b0p = (const float*)d_in[11];
        W1a = (const float*)d_in[12]; al1a = (const float*)d_in[13];
        ar1a = (const float*)d_in[14]; b1a = (const float*)d_in[15];
        W1p = (const float*)d_in[16]; al1p = (const float*)d_in[17];
        ar1p = (const float*)d_in[18]; b1p = (const float*)d_in[19];
        src = (const int*)d_in[20];
        dst = (const int*)d_in[21];
    }

    float* out = (float*)d_out;

    __half* p_ftH;
    float *p_h, *p_el, *p_er, *p_w_am, *p_w_ph;
    cudaGetSymbolAddress((void**)&p_ftH, g_ftH);
    cudaGetSymbolAddress((void**)&p_h, g_h);
    cudaGetSymbolAddress((void**)&p_el, g_el);
    cudaGetSymbolAddress((void**)&p_er, g_er);
    cudaGetSymbolAddress((void**)&p_w_am, g_w_am);
    cudaGetSymbolAddress((void**)&p_w_ph, g_w_ph);

    cudaFuncSetAttribute(gemm_tf32_kernel, cudaFuncAttributeMaxDynamicSharedMemorySize, GEMM_SMEM_BYTES);

    const int TB = 256;
    int gb_nodes = (N_NODES + TB - 1) / TB;
    int gb_edges = (N_EDGES + TB - 1) / TB;
    int gb_warp_nodes = (N_NODES * 32 + TB - 1) / TB;
    int gemm_blocks = (N_NODES + 127) / 128;

    // CSR build (shared by all 4 convs)
    zero_counts_kernel<<<gb_nodes, TB>>>();
    hist_kernel<<<gb_edges, TB>>>(dst);
    scan_partial_kernel<<<SCAN_NB, 256>>>();
    scan_bsum_kernel<<<1, 64>>>();
    scan_write_kernel<<<SCAN_NB, SCAN_B>>>();
    scatter_kernel<<<gb_edges, TB>>>(src, dst, am_exist, exist);

    const __half2* p_ftH2 = reinterpret_cast<const __half2*>(p_ftH);

    for (int br = 0; br < 2; br++) {
        const float* x  = br ? x_ph : x_am;
        const float* ew = br ? p_w_ph : p_w_am;
        const float* W0 = br ? W0p : W0a;
        const float* al0 = br ? al0p : al0a;
        const float* ar0 = br ? ar0p : ar0a;
        const float* b0 = br ? b0p : b0a;
        const float* W1 = br ? W1p : W1a;
        const float* al1 = br ? al1p : al1a;
        const float* ar1 = br ? ar1p : ar1a;
        const float* b1 = br ? b1p : b1a;
        float* out_br = out + (size_t)br * N_NODES * OUTF;

        // layer 0
        gemm_tf32_kernel<<<gemm_blocks, 256, GEMM_SMEM_BYTES>>>(x, W0, al0, ar0, p_ftH, p_el, p_er, N_NODES);
        fused_agg_kernel<false><<<gb_warp_nodes, TB>>>(p_ftH2, p_el, p_er, ew, b0, p_h);

        // layer 1
        gemm_tf32_kernel<<<gemm_blocks, 256, GEMM_SMEM_BYTES>>>(p_h, W1, al1, ar1, p_ftH, p_el, p_er, N_NODES);
        fused_agg_kernel<true><<<gb_warp_nodes, TB>>>(p_ftH2, p_el, p_er, ew, b1, out_br);
    }
}

// round 14
// speedup vs baseline: 1.2521x; 1.0763x over previous
#include <cuda_runtime.h>
#include <cuda_bf16.h>
#include <cuda_fp16.h>
#include <math.h>
#include <stdint.h>

#define N_NODES 50000
#define N_EDGES 800000
#define DIM 128
#define HEADS 4
#define OUTF 32
#define NEG_SLOPE 0.2f

#define SCAN_B 1024
#define SCAN_NB ((N_NODES + SCAN_B - 1) / SCAN_B)   // 49

// ---------------- scratch ----------------
__device__ int    g_counts[N_NODES];
__device__ int    g_rowptr[N_NODES + 1];
__device__ int    g_cursor[N_NODES];
__device__ int    g_colsrc[N_EDGES];
__device__ float  g_w_am[N_EDGES];
__device__ float  g_w_ph[N_EDGES];
__device__ __half g_ftH[N_NODES * DIM];     // fp16 features (gather payload)
__device__ float  g_h[N_NODES * DIM];       // fp32 hidden (GEMM input)
__device__ float  g_el[N_NODES * HEADS];
__device__ float  g_er[N_NODES * HEADS];
__device__ int    g_bsum[SCAN_NB];
__device__ int    g_bsumex[SCAN_NB];

__device__ __forceinline__ uint32_t tf32_rna(float x) {
    uint32_t r;
    asm("cvt.rna.tf32.f32 %0, %1;" : "=r"(r) : "f"(x));
    return r;
}

// ---------------- CSR build ----------------
__global__ void zero_counts_kernel() {
    int i = blockIdx.x * blockDim.x + threadIdx.x;
    if (i < N_NODES) g_counts[i] = 0;
}

__global__ void hist_kernel(const int* __restrict__ dst) {
    int e = blockIdx.x * blockDim.x + threadIdx.x;
    if (e < N_EDGES) atomicAdd(&g_counts[dst[e]], 1);
}

__global__ void scan_partial_kernel() {
    __shared__ int smem[256];
    int b = blockIdx.x, t = threadIdx.x;
    int base = b * SCAN_B;
    int s = 0;
    #pragma unroll
    for (int j = 0; j < 4; j++) {
        int i = base + t + j * 256;
        if (i < N_NODES) s += g_counts[i];
    }
    smem[t] = s;
    __syncthreads();
    for (int off = 128; off > 0; off >>= 1) {
        if (t < off) smem[t] += smem[t + off];
        __syncthreads();
    }
    if (t == 0) g_bsum[b] = smem[0];
}

__global__ void scan_bsum_kernel() {
    __shared__ int smem[64];
    int t = threadIdx.x;
    int v = (t < SCAN_NB) ? g_bsum[t] : 0;
    smem[t] = v;
    __syncthreads();
    #pragma unroll
    for (int off = 1; off < 64; off <<= 1) {
        int x = (t >= off) ? smem[t - off] : 0;
        __syncthreads();
        smem[t] += x;
        __syncthreads();
    }
    if (t < SCAN_NB) g_bsumex[t] = smem[t] - v;
}

__global__ void scan_write_kernel() {
    __shared__ int smem[SCAN_B];
    int b = blockIdx.x, t = threadIdx.x;
    int i = b * SCAN_B + t;
    int v = (i < N_NODES) ? g_counts[i] : 0;
    smem[t] = v;
    __syncthreads();
    #pragma unroll
    for (int off = 1; off < SCAN_B; off <<= 1) {
        int x = (t >= off) ? smem[t - off] : 0;
        __syncthreads();
        smem[t] += x;
        __syncthreads();
    }
    int excl = smem[t] - v + g_bsumex[b];
    if (i < N_NODES) {
        g_rowptr[i] = excl;
        g_cursor[i] = excl;
        if (i == N_NODES - 1) g_rowptr[N_NODES] = excl + v;
    }
}

__global__ void scatter_kernel(const int* __restrict__ src, const int* __restrict__ dst,
                               const float* __restrict__ am_w, const float* __restrict__ ph_w) {
    int e = blockIdx.x * blockDim.x + threadIdx.x;
    if (e >= N_EDGES) return;
    int d = dst[e];
    int pos = atomicAdd(&g_cursor[d], 1);
    g_colsrc[pos] = src[e];
    g_w_am[pos] = am_w[e];
    g_w_ph[pos] = ph_w[e];
}

// ---------------- tf32 mma.sync GEMM + fused el/er epilogue, fp16 ft output ----------------
#define A_STRIDE 132
#define W_STRIDE 136
#define GEMM_SMEM_FLOATS (128 * A_STRIDE + 128 * W_STRIDE + 256)
#define GEMM_SMEM_BYTES (GEMM_SMEM_FLOATS * 4)

__global__ void __launch_bounds__(256, 1) gemm_tf32_kernel(
    const float* __restrict__ A, const float* __restrict__ W,
    const float* __restrict__ al, const float* __restrict__ ar,
    __half* __restrict__ C, float* __restrict__ el, float* __restrict__ er, int M)
{
    extern __shared__ float sm[];
    float* Asm = sm;
    float* Wsm = sm + 128 * A_STRIDE;
    float* als = Wsm + 128 * W_STRIDE;
    float* ars = als + 128;

    int tid = threadIdx.x;
    int br = blockIdx.x * 128;

    #pragma unroll
    for (int i = 0; i < 16; i++) {
        int idx = tid + i * 256;
        int row = idx >> 5;
        int c4 = (idx & 31) * 4;
        int gr = br + row;
        float4 v = make_float4(0.f, 0.f, 0.f, 0.f);
        if (gr < M) v = *reinterpret_cast<const float4*>(&A[(size_t)gr * 128 + c4]);
        float* p = &Asm[row * A_STRIDE + c4];
        p[0] = __uint_as_float(tf32_rna(v.x));
        p[1] = __uint_as_float(tf32_rna(v.y));
        p[2] = __uint_as_float(tf32_rna(v.z));
        p[3] = __uint_as_float(tf32_rna(v.w));
    }
    #pragma unroll
    for (int i = 0; i < 16; i++) {
        int idx = tid + i * 256;
        int row = idx >> 5;
        int c4 = (idx & 31) * 4;
        float4 v = *reinterpret_cast<const float4*>(&W[(size_t)row * 128 + c4]);
        float* p = &Wsm[row * W_STRIDE + c4];
        p[0] = __uint_as_float(tf32_rna(v.x));
        p[1] = __uint_as_float(tf32_rna(v.y));
        p[2] = __uint_as_float(tf32_rna(v.z));
        p[3] = __uint_as_float(tf32_rna(v.w));
    }
    if (tid < 32) {
        *reinterpret_cast<float4*>(&als[tid * 4]) = *reinterpret_cast<const float4*>(&al[tid * 4]);
        *reinterpret_cast<float4*>(&ars[tid * 4]) = *reinterpret_cast<const float4*>(&ar[tid * 4]);
    }
    __syncthreads();

    int w = tid >> 5;
    int lane = tid & 31;
    int g = lane >> 2;
    int q = lane & 3;
    int lrow0 = w * 16 + g;
    int lrow1 = lrow0 + 8;

    float acc[16][4];
    #pragma unroll
    for (int j = 0; j < 16; j++) {
        acc[j][0] = 0.f; acc[j][1] = 0.f; acc[j][2] = 0.f; acc[j][3] = 0.f;
    }

    #pragma unroll
    for (int kk = 0; kk < 16; kk++) {
        int k0 = kk * 8;
        uint32_t a0 = __float_as_uint(Asm[lrow0 * A_STRIDE + k0 + q]);
        uint32_t a1 = __float_as_uint(Asm[lrow1 * A_STRIDE + k0 + q]);
        uint32_t a2 = __float_as_uint(Asm[lrow0 * A_STRIDE + k0 + q + 4]);
        uint32_t a3 = __float_as_uint(Asm[lrow1 * A_STRIDE + k0 + q + 4]);
        #pragma unroll
        for (int j = 0; j < 16; j++) {
            uint32_t b0 = __float_as_uint(Wsm[(k0 + q) * W_STRIDE + 8 * j + g]);
            uint32_t b1 = __float_as_uint(Wsm[(k0 + q + 4) * W_STRIDE + 8 * j + g]);
            asm volatile(
                "mma.sync.aligned.m16n8k8.row.col.f32.tf32.tf32.f32 "
                "{%0,%1,%2,%3}, {%4,%5,%6,%7}, {%8,%9}, {%0,%1,%2,%3};"
                : "+f"(acc[j][0]), "+f"(acc[j][1]), "+f"(acc[j][2]), "+f"(acc[j][3])
                : "r"(a0), "r"(a1), "r"(a2), "r"(a3), "r"(b0), "r"(b1));
        }
    }

    int grow0 = br + lrow0;
    int grow1 = br + lrow1;

    float el0[4] = {0.f, 0.f, 0.f, 0.f}, er0[4] = {0.f, 0.f, 0.f, 0.f};
    float el1[4] = {0.f, 0.f, 0.f, 0.f}, er1[4] = {0.f, 0.f, 0.f, 0.f};

    __half2* Ch = reinterpret_cast<__half2*>(C);

    #pragma unroll
    for (int j = 0; j < 16; j++) {
        int c = 8 * j + 2 * q;
        int h = j >> 2;
        float w0 = als[c], w1 = als[c + 1];
        float r0 = ars[c], r1 = ars[c + 1];
        el0[h] += acc[j][0] * w0 + acc[j][1] * w1;
        er0[h] += acc[j][0] * r0 + acc[j][1] * r1;
        el1[h] += acc[j][2] * w0 + acc[j][3] * w1;
        er1[h] += acc[j][2] * r0 + acc[j][3] * r1;
        int h2idx = c >> 1;   // 4j + q
        if (grow0 < M)
            Ch[(size_t)grow0 * 64 + h2idx] = __floats2half2_rn(acc[j][0], acc[j][1]);
        if (grow1 < M)
            Ch[(size_t)grow1 * 64 + h2idx] = __floats2half2_rn(acc[j][2], acc[j][3]);
    }

    #pragma unroll
    for (int h = 0; h < 4; h++) {
        #pragma unroll
        for (int off = 1; off < 4; off <<= 1) {
            el0[h] += __shfl_xor_sync(0xffffffffu, el0[h], off);
            er0[h] += __shfl_xor_sync(0xffffffffu, er0[h], off);
            el1[h] += __shfl_xor_sync(0xffffffffu, el1[h], off);
            er1[h] += __shfl_xor_sync(0xffffffffu, er1[h], off);
        }
    }
    if (q == 0) {
        if (grow0 < M) {
            *reinterpret_cast<float4*>(&el[grow0 * 4]) = make_float4(el0[0], el0[1], el0[2], el0[3]);
            *reinterpret_cast<float4*>(&er[grow0 * 4]) = make_float4(er0[0], er0[1], er0[2], er0[3]);
        }
        if (grow1 < M) {
            *reinterpret_cast<float4*>(&el[grow1 * 4]) = make_float4(el1[0], el1[1], el1[2], el1[3]);
            *reinterpret_cast<float4*>(&er[grow1 * 4]) = make_float4(er1[0], er1[1], er1[2], er1[3]);
        }
    }
}

// ---------------- leaky ----------------
__device__ __forceinline__ float leaky(float v) {
    return v > 0.f ? v : NEG_SLOPE * v;
}

// ---------------- fused softmax + aggregation: warp per node ----------------
// Lane covers global features 4*lane .. 4*lane+3 (all within head = lane>>3).
// Phase A: lane-parallel alpha compute, staged to smem (src + float4 alpha).
// Phase B: LDS broadcast + one LDG.64 per edge per lane.
#define AGG_WARPS 8
template <bool LAYER1>
__global__ void __launch_bounds__(AGG_WARPS * 32) fused_agg_kernel(
    const uint2* __restrict__ ft2,           // g_ftH rows as 32 x uint2 (8B = 4 halves)
    const float* __restrict__ el, const float* __restrict__ er,
    const float* __restrict__ w,
    const float* __restrict__ bias,
    float* __restrict__ out)
{
    __shared__ int   s_src[AGG_WARPS][32];
    __shared__ float s_al[AGG_WARPS][32 * 4];

    int i = (blockIdx.x * blockDim.x + threadIdx.x) >> 5;
    int wslot = threadIdx.x >> 5;
    int lane = threadIdx.x & 31;
    if (i >= N_NODES) return;
    int beg = g_rowptr[i], end = g_rowptr[i + 1];
    float4 e4 = *reinterpret_cast<const float4*>(er + i * 4);
    int h = lane >> 3;   // head owned by this lane

    float acc0 = 0.f, acc1 = 0.f, acc2 = 0.f, acc3 = 0.f;
    float d0 = 0.f, d1 = 0.f, d2 = 0.f, d3 = 0.f;

    for (int chunk = beg; chunk < end; chunk += 32) {
        int n = end - chunk;
        if (n > 32) n = 32;

        // ---- phase A: lane-parallel alpha, stage to smem ----
        int s = 0;
        float a0 = 0.f, a1 = 0.f, a2 = 0.f, a3 = 0.f;
        if (lane < n) {
            int e = chunk + lane;
            s = g_colsrc[e];
            float we = w[e];
            float4 lv = *reinterpret_cast<const float4*>(el + s * 4);
            float x0 = __expf(leaky(lv.x + e4.x));
            float x1 = __expf(leaky(lv.y + e4.y));
            float x2 = __expf(leaky(lv.z + e4.z));
            float x3 = __expf(leaky(lv.w + e4.w));
            d0 += x0; d1 += x1; d2 += x2; d3 += x3;
            a0 = x0 * we; a1 = x1 * we; a2 = x2 * we; a3 = x3 * we;
        }
        s_src[wslot][lane] = s;
        *reinterpret_cast<float4*>(&s_al[wslot][lane * 4]) = make_float4(a0, a1, a2, a3);
        __syncwarp();

        // ---- phase B: LDS broadcast + LDG.64 gather, 2-way unrolled ----
        int j = 0;
        for (; j + 1 < n; j += 2) {
            int s0 = s_src[wslot][j];
            int s1 = s_src[wslot][j + 1];
            float aa = s_al[wslot][j * 4 + h];
            float ab = s_al[wslot][(j + 1) * 4 + h];
            uint2 r0 = ft2[(size_t)s0 * 32 + lane];
            uint2 r1 = ft2[(size_t)s1 * 32 + lane];
            float2 lo0 = __half22float2(*reinterpret_cast<__half2*>(&r0.x));
            float2 hi0 = __half22float2(*reinterpret_cast<__half2*>(&r0.y));
            float2 lo1 = __half22float2(*reinterpret_cast<__half2*>(&r1.x));
            float2 hi1 = __half22float2(*reinterpret_cast<__half2*>(&r1.y));
            acc0 += aa * lo0.x + ab * lo1.x;
            acc1 += aa * lo0.y + ab * lo1.y;
            acc2 += aa * hi0.x + ab * hi1.x;
            acc3 += aa * hi0.y + ab * hi1.y;
        }
        if (j < n) {
            int s0 = s_src[wslot][j];
            float aa = s_al[wslot][j * 4 + h];
            uint2 r0 = ft2[(size_t)s0 * 32 + lane];
            float2 lo0 = __half22float2(*reinterpret_cast<__half2*>(&r0.x));
            float2 hi0 = __half22float2(*reinterpret_cast<__half2*>(&r0.y));
            acc0 += aa * lo0.x;
            acc1 += aa * lo0.y;
            acc2 += aa * hi0.x;
            acc3 += aa * hi0.y;
        }
        __syncwarp();
    }

    // reduce denominators across lanes
    #pragma unroll
    for (int off = 16; off > 0; off >>= 1) {
        d0 += __shfl_xor_sync(0xffffffffu, d0, off);
        d1 += __shfl_xor_sync(0xffffffffu, d1, off);
        d2 += __shfl_xor_sync(0xffffffffu, d2, off);
        d3 += __shfl_xor_sync(0xffffffffu, d3, off);
    }
    d0 = fmaxf(d0, 1e-9f); d1 = fmaxf(d1, 1e-9f);
    d2 = fmaxf(d2, 1e-9f); d3 = fmaxf(d3, 1e-9f);
    float dsel = (h == 0) ? d0 : (h == 1) ? d1 : (h == 2) ? d2 : d3;

    float4 b4 = *reinterpret_cast<const float4*>(&bias[lane * 4]);
    float v0 = acc0 / dsel + b4.x;
    float v1 = acc1 / dsel + b4.y;
    float v2 = acc2 / dsel + b4.z;
    float v3 = acc3 / dsel + b4.w;

    if (!LAYER1) {
        float4 o = make_float4(fmaxf(v0, 0.f), fmaxf(v1, 0.f), fmaxf(v2, 0.f), fmaxf(v3, 0.f));
        *reinterpret_cast<float4*>(&out[(size_t)i * 128 + lane * 4]) = o;
    } else {
        // mean over heads: fold lanes with same (lane & 7)
        v0 += __shfl_xor_sync(0xffffffffu, v0, 8);
        v1 += __shfl_xor_sync(0xffffffffu, v1, 8);
        v2 += __shfl_xor_sync(0xffffffffu, v2, 8);
        v3 += __shfl_xor_sync(0xffffffffu, v3, 8);
        v0 += __shfl_xor_sync(0xffffffffu, v0, 16);
        v1 += __shfl_xor_sync(0xffffffffu, v1, 16);
        v2 += __shfl_xor_sync(0xffffffffu, v2, 16);
        v3 += __shfl_xor_sync(0xffffffffu, v3, 16);
        if (lane < 8) {
            float4 o = make_float4(0.25f * v0, 0.25f * v1, 0.25f * v2, 0.25f * v3);
            *reinterpret_cast<float4*>(&out[(size_t)i * 32 + lane * 4]) = o;
        }
    }
}

// ---------------- launch ----------------
extern "C" void kernel_launch(void* const* d_in, const int* in_sizes, int n_in,
                              void* d_out, int out_size) {
    const float *x_am, *x_ph, *exist, *am_exist;
    const int *src, *dst;
    const float *W0a, *al0a, *ar0a, *b0a, *W0p, *al0p, *ar0p, *b0p;
    const float *W1a, *al1a, *ar1a, *b1a, *W1p, *al1p, *ar1p, *b1p;

    x_am = (const float*)d_in[0];
    x_ph = (const float*)d_in[1];
    exist = (const float*)d_in[2];
    am_exist = (const float*)d_in[3];

    if (in_sizes[4] == N_EDGES) {
        src = (const int*)d_in[4];
        dst = (const int*)d_in[5];
        W0a = (const float*)d_in[6];  al0a = (const float*)d_in[7];
        ar0a = (const float*)d_in[8]; b0a = (const float*)d_in[9];
        W0p = (const float*)d_in[10]; al0p = (const float*)d_in[11];
        ar0p = (const float*)d_in[12]; b0p = (const float*)d_in[13];
        W1a = (const float*)d_in[14]; al1a = (const float*)d_in[15];
        ar1a = (const float*)d_in[16]; b1a = (const float*)d_in[17];
        W1p = (const float*)d_in[18]; al1p = (const float*)d_in[19];
        ar1p = (const float*)d_in[20]; b1p = (const float*)d_in[21];
    } else {
        W0a = (const float*)d_in[4];  al0a = (const float*)d_in[5];
        ar0a = (const float*)d_in[6]; b0a = (const float*)d_in[7];
        W0p = (const float*)d_in[8];  al0p = (const float*)d_in[9];
        ar0p = (const float*)d_in[10]; b0p = (const float*)d_in[11];
        W1a = (const float*)d_in[12]; al1a = (const float*)d_in[13];
        ar1a = (const float*)d_in[14]; b1a = (const float*)d_in[15];
        W1p = (const float*)d_in[16]; al1p = (const float*)d_in[17];
        ar1p = (const float*)d_in[18]; b1p = (const float*)d_in[19];
        src = (const int*)d_in[20];
        dst = (const int*)d_in[21];
    }

    float* out = (float*)d_out;

    __half* p_ftH;
    float *p_h, *p_el, *p_er, *p_w_am, *p_w_ph;
    cudaGetSymbolAddress((void**)&p_ftH, g_ftH);
    cudaGetSymbolAddress((void**)&p_h, g_h);
    cudaGetSymbolAddress((void**)&p_el, g_el);
    cudaGetSymbolAddress((void**)&p_er, g_er);
    cudaGetSymbolAddress((void**)&p_w_am, g_w_am);
    cudaGetSymbolAddress((void**)&p_w_ph, g_w_ph);

    cudaFuncSetAttribute(gemm_tf32_kernel, cudaFuncAttributeMaxDynamicSharedMemorySize, GEMM_SMEM_BYTES);

    const int TB = 256;
    int gb_nodes = (N_NODES + TB - 1) / TB;
    int gb_edges = (N_EDGES + TB - 1) / TB;
    int gb_warp_nodes = (N_NODES * 32 + TB - 1) / TB;
    int gemm_blocks = (N_NODES + 127) / 128;

    // CSR build (shared by all 4 convs)
    zero_counts_kernel<<<gb_nodes, TB>>>();
    hist_kernel<<<gb_edges, TB>>>(dst);
    scan_partial_kernel<<<SCAN_NB, 256>>>();
    scan_bsum_kernel<<<1, 64>>>();
    scan_write_kernel<<<SCAN_NB, SCAN_B>>>();
    scatter_kernel<<<gb_edges, TB>>>(src, dst, am_exist, exist);

    const uint2* p_ft2 = reinterpret_cast<const uint2*>(p_ftH);

    for (int br = 0; br < 2; br++) {
        const float* x  = br ? x_ph : x_am;
        const float* ew = br ? p_w_ph : p_w_am;
        const float* W0 = br ? W0p : W0a;
        const float* al0 = br ? al0p : al0a;
        const float* ar0 = br ? ar0p : ar0a;
        const float* b0 = br ? b0p : b0a;
        const float* W1 = br ? W1p : W1a;
        const float* al1 = br ? al1p : al1a;
        const float* ar1 = br ? ar1p : ar1a;
        const float* b1 = br ? b1p : b1a;
        float* out_br = out + (size_t)br * N_NODES * OUTF;

        // layer 0
        gemm_tf32_kernel<<<gemm_blocks, 256, GEMM_SMEM_BYTES>>>(x, W0, al0, ar0, p_ftH, p_el, p_er, N_NODES);
        fused_agg_kernel<false><<<gb_warp_nodes, TB>>>(p_ft2, p_el, p_er, ew, b0, p_h);

        // layer 1
        gemm_tf32_kernel<<<gemm_blocks, 256, GEMM_SMEM_BYTES>>>(p_h, W1, al1, ar1, p_ftH, p_el, p_er, N_NODES);
        fused_agg_kernel<true><<<gb_warp_nodes, TB>>>(p_ft2, p_el, p_er, ew, b1, out_br);
    }
}